// round 1
// baseline (speedup 1.0000x reference)
#include <cuda_runtime.h>
#include <math.h>
#include <stdint.h>

// Problem constants
#define BB   32
#define TY   64
#define TXX  64
#define TTT  64
#define HH   512
#define VSS  32000
#define VTT  32000
#define ROWS 2048          // BB*TY == BB*TTT
#define NCB  250           // 32000 / 128 column blocks

// ---------------- scratch (static device memory; no allocs allowed) --------
__device__ __align__(16) float g_ts[ROWS * HH];          // tanh emission states
__device__ __align__(16) float g_tsn[HH];                // null state
__device__ __align__(16) float g_nullLogits[VSS];
__device__ float g_nullPart[125];
__device__ float g_nullSum;
__device__ __align__(16) float g_partE[NCB * ROWS];      // per-colblock exp-sums (emission)
__device__ __align__(16) float g_partT[NCB * ROWS];      // per-colblock exp-sums (target)
__device__ __align__(16) float g_emGath[ROWS * TXX];     // gathered emission logits
__device__ __align__(16) float g_tgtLogit[ROWS];         // gathered target logits
__device__ unsigned long long g_argmax[ROWS];            // encoded (value, ~idx)

// ---------------- small helpers -------------------------------------------
__device__ __forceinline__ void ffma2(unsigned long long &d,
                                      unsigned long long a,
                                      unsigned long long b) {
    asm("fma.rn.f32x2 %0, %1, %2, %0;" : "+l"(d) : "l"(a), "l"(b));
}
__device__ __forceinline__ unsigned long long pk2(float x) {
    unsigned long long r;
    asm("mov.b64 %0, {%1, %1};" : "=l"(r) : "f"(x));
    return r;
}
__device__ __forceinline__ float2 up2(unsigned long long v) {
    float2 r;
    asm("mov.b64 {%0, %1}, %2;" : "=f"(r.x), "=f"(r.y) : "l"(v));
    return r;
}
__device__ __forceinline__ unsigned long long key64(float x, int col) {
    unsigned u = __float_as_uint(x);
    u = (u & 0x80000000u) ? ~u : (u | 0x80000000u);   // order-preserving map
    return ((unsigned long long)u << 32) | (unsigned)(~(unsigned)col);
}

// ---------------- init: reset argmax accumulators (graph replays!) ---------
__global__ void k_init() {
    int i = blockIdx.x * blockDim.x + threadIdx.x;
    if (i < ROWS) g_argmax[i] = 0ull;
}

// ---------------- null state: tsn = tanh(y_null @ W_em + b_em) -------------
__global__ void k_tsn(const float* __restrict__ yn,
                      const float* __restrict__ W,
                      const float* __restrict__ bias) {
    __shared__ float y[HH];
    int t = threadIdx.x;                 // 512 threads
    y[t] = yn[t];
    __syncthreads();
    float acc = bias[t];
#pragma unroll 8
    for (int k = 0; k < HH; k++) acc += y[k] * W[k * HH + t];
    g_tsn[t] = tanhf(acc);
}

// ---------------- null logits over VS + partial exp-sums -------------------
__global__ void k_null(const float* __restrict__ W,
                       const float* __restrict__ bias) {
    __shared__ float tn[HH];
    __shared__ float red[256];
    int t = threadIdx.x;                 // 256 threads, 125 blocks
    tn[t] = g_tsn[t];
    tn[t + 256] = g_tsn[t + 256];
    __syncthreads();
    int c = blockIdx.x * 256 + t;
    float acc = bias[c];
#pragma unroll 8
    for (int k = 0; k < HH; k++) acc += tn[k] * W[k * VSS + c];
    g_nullLogits[c] = acc;
    red[t] = __expf(acc);
    __syncthreads();
    for (int s = 128; s > 0; s >>= 1) {
        if (t < s) red[t] += red[t + s];
        __syncthreads();
    }
    if (t == 0) g_nullPart[blockIdx.x] = red[0];
}

__global__ void k_nullred() {
    __shared__ float red[128];
    int t = threadIdx.x;
    float s = 0.f;
    for (int i = t; i < 125; i += 128) s += g_nullPart[i];
    red[t] = s;
    __syncthreads();
    for (int st = 64; st > 0; st >>= 1) {
        if (t < st) red[t] += red[t + st];
        __syncthreads();
    }
    if (t == 0) g_nullSum = red[0];
}

// ---------------- fused GEMM ------------------------------------------------
// MODE 0: ts = tanh(y_hidden @ W_em + b_em)           (N = 512,  store g_ts)
// MODE 1: emission: Σexp per row + source gather      (N = 32000)
// MODE 2: target:   Σexp per row + target gather + argmax
// Tile: BM=128, BN=128, BK=16, 256 threads, 8x8 micro (split 4+4 rows/cols),
// inner loop = fma.rn.f32x2.
template <int MODE>
__global__ void __launch_bounds__(256) gemm_fused(
        const float* __restrict__ A, const float* __restrict__ Bmat,
        const float* __restrict__ bias, const int* __restrict__ gidx, int N) {
    __shared__ __align__(16) float As[16][132];
    __shared__ __align__(16) float Bs[16][128];
    __shared__ __align__(16) unsigned long long sred[128 * 16]; // also float view
    __shared__ int sidx[128];

    const int tid = threadIdx.x;
    const int tx = tid & 15, ty = tid >> 4;
    const int c0 = blockIdx.x * 128;
    const int r0 = blockIdx.y * 128;
    const float* Ap = (MODE == 1) ? (const float*)g_ts : A;

    unsigned long long acc[8][4];
#pragma unroll
    for (int i = 0; i < 8; i++)
#pragma unroll
        for (int q = 0; q < 4; q++) acc[i][q] = 0ull;

    // preload first k-tile into registers
    float4 pa[2], pb[2];
    {
        const int kbase = 0;
#pragma unroll
        for (int u = 0; u < 2; u++) {
            int v = tid + u * 256;
            int rr = v >> 2, kk4 = (v & 3) << 2;
            pa[u] = *(const float4*)(Ap + (size_t)(r0 + rr) * HH + kbase + kk4);
            int kb = v >> 5, cv = (v & 31) << 2;
            pb[u] = *(const float4*)(Bmat + (size_t)(kbase + kb) * N + c0 + cv);
        }
    }

    for (int kt = 0; kt < 32; kt++) {
        __syncthreads();          // previous compute done
#pragma unroll
        for (int u = 0; u < 2; u++) {
            int v = tid + u * 256;
            int rr = v >> 2, kk4 = (v & 3) << 2;
            As[kk4 + 0][rr] = pa[u].x;
            As[kk4 + 1][rr] = pa[u].y;
            As[kk4 + 2][rr] = pa[u].z;
            As[kk4 + 3][rr] = pa[u].w;
            int kb = v >> 5, cv = (v & 31) << 2;
            *(float4*)&Bs[kb][cv] = pb[u];
        }
        __syncthreads();          // tiles ready
        if (kt + 1 < 32) {
            const int kbase = (kt + 1) * 16;
#pragma unroll
            for (int u = 0; u < 2; u++) {
                int v = tid + u * 256;
                int rr = v >> 2, kk4 = (v & 3) << 2;
                pa[u] = *(const float4*)(Ap + (size_t)(r0 + rr) * HH + kbase + kk4);
                int kb = v >> 5, cv = (v & 31) << 2;
                pb[u] = *(const float4*)(Bmat + (size_t)(kbase + kb) * N + c0 + cv);
            }
        }
#pragma unroll
        for (int kk = 0; kk < 16; kk++) {
            float4 a0 = *(const float4*)&As[kk][ty * 4];
            float4 a1 = *(const float4*)&As[kk][64 + ty * 4];
            ulonglong2 b0 = *(const ulonglong2*)&Bs[kk][tx * 4];
            ulonglong2 b1 = *(const ulonglong2*)&Bs[kk][64 + tx * 4];
            float av[8] = {a0.x, a0.y, a0.z, a0.w, a1.x, a1.y, a1.z, a1.w};
#pragma unroll
            for (int i = 0; i < 8; i++) {
                unsigned long long ap = pk2(av[i]);
                ffma2(acc[i][0], ap, b0.x);
                ffma2(acc[i][1], ap, b0.y);
                ffma2(acc[i][2], ap, b1.x);
                ffma2(acc[i][3], ap, b1.y);
            }
        }
    }

    // ---- epilogue ----
    if (MODE != 0) {
        if (tid < 128) sidx[tid] = gidx[r0 + tid];   // sources/targets, flat row-indexed
    }

    float logit[8][8];
#pragma unroll
    for (int i = 0; i < 8; i++)
#pragma unroll
        for (int q = 0; q < 4; q++) {
            float2 p = up2(acc[i][q]);
            logit[i][2 * q] = p.x;
            logit[i][2 * q + 1] = p.y;
        }
    float bcol[8];
#pragma unroll
    for (int jj = 0; jj < 8; jj++)
        bcol[jj] = bias[c0 + (jj >> 2) * 64 + tx * 4 + (jj & 3)];
#pragma unroll
    for (int i = 0; i < 8; i++)
#pragma unroll
        for (int jj = 0; jj < 8; jj++) logit[i][jj] += bcol[jj];

    if (MODE == 0) {
#pragma unroll
        for (int i = 0; i < 8; i++) {
            int r = r0 + (i >> 2) * 64 + ty * 4 + (i & 3);
#pragma unroll
            for (int jj = 0; jj < 8; jj++) {
                int c = c0 + (jj >> 2) * 64 + tx * 4 + (jj & 3);
                g_ts[(size_t)r * HH + c] = tanhf(logit[i][jj]);
            }
        }
        return;
    }

    __syncthreads();   // sidx visible

    if (MODE == 1) {
        // gather source columns: rows of group g all lie in batch (r0/64 + g)
#pragma unroll
        for (int g = 0; g < 2; g++) {
            for (int j = 0; j < 64; j++) {
                int c = sidx[g * 64 + j];
                int d = c - c0 - tx * 4;
                if (d >= 0 && d < 4) {
#pragma unroll
                    for (int i2 = 0; i2 < 4; i2++)
                        g_emGath[(r0 + g * 64 + ty * 4 + i2) * 64 + j] =
                            logit[g * 4 + i2][d];
                }
                d -= 64;
                if (d >= 0 && d < 4) {
#pragma unroll
                    for (int i2 = 0; i2 < 4; i2++)
                        g_emGath[(r0 + g * 64 + ty * 4 + i2) * 64 + j] =
                            logit[g * 4 + i2][4 + d];
                }
            }
        }
    } else {
        // gather target logit (one column per row)
#pragma unroll
        for (int i = 0; i < 8; i++) {
            int rl = (i >> 2) * 64 + ty * 4 + (i & 3);
            int c = sidx[rl];
            int d = c - c0 - tx * 4;
            if (d >= 0 && d < 4) g_tgtLogit[r0 + rl] = logit[i][d];
            d -= 64;
            if (d >= 0 && d < 4) g_tgtLogit[r0 + rl] = logit[i][4 + d];
        }
    }

    // per-row exp sums (deterministic: one partial per (colblock,row))
    float* fred = (float*)sred;
#pragma unroll
    for (int i = 0; i < 8; i++) {
        int rl = (i >> 2) * 64 + ty * 4 + (i & 3);
        float s = 0.f;
#pragma unroll
        for (int jj = 0; jj < 8; jj++) s += __expf(logit[i][jj]);
        fred[rl * 16 + tx] = s;
    }
    __syncthreads();
    if (tid < 128) {
        float s = 0.f;
#pragma unroll
        for (int t2 = 0; t2 < 16; t2++) s += fred[tid * 16 + t2];
        if (MODE == 1) g_partE[(size_t)blockIdx.x * ROWS + r0 + tid] = s;
        else           g_partT[(size_t)blockIdx.x * ROWS + r0 + tid] = s;
    }

    if (MODE == 2) {
        __syncthreads();   // fred reads done before reuse as u64
#pragma unroll
        for (int i = 0; i < 8; i++) {
            int rl = (i >> 2) * 64 + ty * 4 + (i & 3);
            unsigned long long m = 0ull;
#pragma unroll
            for (int jj = 0; jj < 8; jj++) {
                int c = c0 + (jj >> 2) * 64 + tx * 4 + (jj & 3);
                unsigned long long k = key64(logit[i][jj], c);
                m = (k > m) ? k : m;
            }
            sred[rl * 16 + tx] = m;
        }
        __syncthreads();
        if (tid < 128) {
            unsigned long long m = 0ull;
#pragma unroll
            for (int t2 = 0; t2 < 16; t2++) {
                unsigned long long k = sred[tid * 16 + t2];
                m = (k > m) ? k : m;
            }
            atomicMax(&g_argmax[r0 + tid], m);
        }
    }
}

// ---------------- pack outputs ---------------------------------------------
__global__ void k_pack(const int* __restrict__ sources,
                       const int* __restrict__ tlen,
                       float* __restrict__ out) {
    int row = blockIdx.x * 128 + threadIdx.x;   // 0..2047
    int b = row >> 6, t = row & 63;
    float sE = 0.f, sT = 0.f;
#pragma unroll 10
    for (int cb = 0; cb < NCB; cb++) {
        sE += g_partE[(size_t)cb * ROWS + row];
        sT += g_partT[(size_t)cb * ROWS + row];
    }
    float invE = 1.f / sE;
    float ns = 1.f / g_nullSum;
    // emission_prob (B, 2*TY, TX): t<64 -> gathered softmax, t>=64 -> null row
    size_t eb = (size_t)b * 8192;
    for (int j = 0; j < 64; j++)
        out[eb + t * 64 + j] = __expf(g_emGath[row * 64 + j]) * invE;
    for (int j = 0; j < 64; j++)
        out[eb + 4096 + t * 64 + j] = __expf(g_nullLogits[sources[b * 64 + j]]) * ns;
    // reconstruction
    float mask = (t < tlen[b]) ? 1.f : 0.f;
    float tl = g_tgtLogit[row];
    out[262144 + row] = mask * (__expf(tl) / sT);
    out[264192 + row] = mask * (tl - logf(sT));
    unsigned low = (unsigned)(g_argmax[row] & 0xFFFFFFFFull);
    out[266240 + row] = (float)(~low);
}

// ---------------- launch -----------------------------------------------------
extern "C" void kernel_launch(void* const* d_in, const int* in_sizes, int n_in,
                              void* d_out, int out_size) {
    const float* y_hidden   = (const float*)d_in[0];
    const float* y_null     = (const float*)d_in[1];
    const float* tgt_state  = (const float*)d_in[2];
    const float* W_em       = (const float*)d_in[3];
    const float* b_em       = (const float*)d_in[4];
    const float* W_sv       = (const float*)d_in[5];
    const float* b_sv       = (const float*)d_in[6];
    const float* W_tv       = (const float*)d_in[7];
    const float* b_tv       = (const float*)d_in[8];
    const int*   sources    = (const int*)d_in[9];
    const int*   targets    = (const int*)d_in[10];
    const int*   tlen       = (const int*)d_in[11];
    float* out = (float*)d_out;

    k_init<<<2, 1024>>>();
    k_tsn<<<1, 512>>>(y_null, W_em, b_em);
    gemm_fused<0><<<dim3(4, 16), 256>>>(y_hidden, W_em, b_em, nullptr, HH);
    k_null<<<125, 256>>>(W_sv, b_sv);
    k_nullred<<<1, 128>>>();
    gemm_fused<1><<<dim3(NCB, 16), 256>>>(nullptr, W_sv, b_sv, sources, VSS);
    gemm_fused<2><<<dim3(NCB, 16), 256>>>(tgt_state, W_tv, b_tv, targets, VTT);
    k_pack<<<16, 128>>>(sources, tlen, out);
}